// round 16
// baseline (speedup 1.0000x reference)
#include <cuda_runtime.h>

#define NQ     10
#define CDEPTH 6
#define NCLS   16
#define CBATCH 65536

// Gate tables. Layers 1..5 use fast-Givens: t = tan(half-angle), with the
// global product of cosines folded into g_C2 (applied to expectations).
__device__ float g_c[64];
__device__ float g_s[64];
__device__ float g_t[64];
__device__ float g_C2;

__global__ void precompute_gates(const float* __restrict__ params) {
    __shared__ float cs[64];
    int t = threadIdx.x;
    if (t < CDEPTH * NQ) {
        float s, c;
        sincosf(0.5f * params[t], &s, &c);
        g_c[t] = c;
        g_s[t] = s;
        g_t[t] = s / c;
        cs[t] = c;
    }
    __syncthreads();
    if (t == 0) {
        float C = 1.f;
        for (int i = NQ; i < CDEPTH * NQ; i++) C *= cs[i];   // layers 1..5 only
        g_C2 = C * C;
    }
}

// ---- packed f32x2 helpers (Blackwell sm_103a) ----
static __device__ __forceinline__ unsigned long long pk2(float lo, float hi) {
    unsigned long long r;
    asm("mov.b64 %0, {%1, %2};" : "=l"(r) : "f"(lo), "f"(hi));
    return r;
}
static __device__ __forceinline__ float2 upk2(unsigned long long v) {
    float2 r;
    asm("mov.b64 {%0, %1}, %2;" : "=f"(r.x), "=f"(r.y) : "l"(v));
    return r;
}
static __device__ __forceinline__ unsigned long long swap2(unsigned long long v) {
    float2 t = upk2(v);
    return pk2(t.y, t.x);
}
static __device__ __forceinline__ unsigned long long mul2(unsigned long long a, unsigned long long b) {
    unsigned long long r;
    asm("mul.rn.f32x2 %0, %1, %2;" : "=l"(r) : "l"(a), "l"(b));
    return r;
}
static __device__ __forceinline__ unsigned long long fma2(unsigned long long a, unsigned long long b,
                                                          unsigned long long c) {
    unsigned long long r;
    asm("fma.rn.f32x2 %0, %1, %2, %3;" : "=l"(r) : "l"(a), "l"(b), "l"(c));
    return r;
}

// One warp per batch element; 1024 complex amps as 32 packed f32x2 per lane.
// Bit layout (flat amp index bit 9-q <-> wire q):
//   lane bits 4..1 : wires 0..3  (SHFL gates)
//   lane bit 0     : re/im component (passive)
//   pack bit       : wire 4      (local half-swap gate)
//   reg bits 4..0  : wires 5..9  (local Givens pairs)
// Layers 1..5 use fast-Givens; the cos product is restored via g_C2 at the end.
// Init builds the complex product tree IN-PLACE in a[] (packed re,im) so the
// register peak stays ~80 -> 3 CTAs/SM (launch_bounds caps regs at 85).
__global__ void __launch_bounds__(256, 3) qsim_kernel(
    const float* __restrict__ x,
    const float* __restrict__ w_cls,
    const float* __restrict__ b_cls,
    float* __restrict__ out)
{
    const int lane = threadIdx.x & 31;
    const int warp = threadIdx.x >> 5;
    const int e    = blockIdx.x * 8 + warp;
    const int comp = lane & 1;            // 0 = re, 1 = im

    // ---------- init: RX(x) then RY(layer 0) -- product state ----------
    // per-wire 2-vector (bit=0, bit=1): v0 = (c*cx, s*sx), v1 = (s*cx, -c*sx)
    float v0r = 1.f, v0i = 0.f, v1r = 0.f, v1i = 0.f;
    if (lane < NQ) {
        float cx, sx;
        sincosf(0.5f * x[e * NQ + lane], &sx, &cx);
        float c = g_c[lane], s = g_s[lane];
        v0r = c * cx;  v0i = s * sx;
        v1r = s * cx;  v1i = -c * sx;
    }

    // lane-resident complex product over lane wires 0..3 (wire q <-> lane bit 4-q)
    // broadcasts consumed one wire at a time (4 floats live, not 40)
    float Lr, Li;
    {
        float b0r = __shfl_sync(0xFFFFFFFFu, v0r, 0);
        float b0i = __shfl_sync(0xFFFFFFFFu, v0i, 0);
        float b1r = __shfl_sync(0xFFFFFFFFu, v1r, 0);
        float b1i = __shfl_sync(0xFFFFFFFFu, v1i, 0);
        int b = (lane >> 4) & 1;
        Lr = b ? b1r : b0r;
        Li = b ? b1i : b0i;
        #pragma unroll
        for (int q = 1; q < 4; q++) {
            b0r = __shfl_sync(0xFFFFFFFFu, v0r, q);
            b0i = __shfl_sync(0xFFFFFFFFu, v0i, q);
            b1r = __shfl_sync(0xFFFFFFFFu, v1r, q);
            b1i = __shfl_sync(0xFFFFFFFFu, v1i, q);
            int bb = (lane >> (4 - q)) & 1;
            float br = bb ? b1r : b0r;
            float bi = bb ? b1i : b0i;
            float nr = fmaf(-Li, bi, Lr * br);
            float ni = fmaf( Li, br, Lr * bi);
            Lr = nr; Li = ni;
        }
    }

    // in-place complex product tree over reg wires 5..9, a[k] = packed (re,im)
    unsigned long long a[32];
    a[0] = pk2(Lr, Li);
    #pragma unroll
    for (int q = 5; q < NQ; q++) {
        const float c0r = __shfl_sync(0xFFFFFFFFu, v0r, q);
        const float c0i = __shfl_sync(0xFFFFFFFFu, v0i, q);
        const float c1r = __shfl_sync(0xFFFFFFFFu, v1r, q);
        const float c1i = __shfl_sync(0xFFFFFFFFu, v1i, q);
        const unsigned long long W0a = pk2(c0r, c0r);
        const unsigned long long W0b = pk2(-c0i, c0i);
        const unsigned long long W1a = pk2(c1r, c1r);
        const unsigned long long W1b = pk2(-c1i, c1i);
        const int m = 1 << (q - 5);
        #pragma unroll
        for (int k = m - 1; k >= 0; k--) {        // descending k: write-safe
            unsigned long long p  = a[k];
            unsigned long long sp = swap2(p);     // (im, re)
            a[2 * k + 1] = fma2(W1a, p, mul2(W1b, sp));  // p * w1 (complex)
            a[2 * k]     = fma2(W0a, p, mul2(W0b, sp));  // p * w0 (complex)
        }
    }

    // wire-4 fold + component selection (local per j):
    //   lo = al0*re + be0*im,  hi = al1*re + be1*im
    {
        const float c0r = __shfl_sync(0xFFFFFFFFu, v0r, 4);
        const float c0i = __shfl_sync(0xFFFFFFFFu, v0i, 4);
        const float c1r = __shfl_sync(0xFFFFFFFFu, v1r, 4);
        const float c1i = __shfl_sync(0xFFFFFFFFu, v1i, 4);
        const float alLo = comp ? c0i : c0r;
        const float beLo = comp ? c0r : -c0i;
        const float alHi = comp ? c1i : c1r;
        const float beHi = comp ? c1r : -c1i;
        const unsigned long long AL = pk2(alLo, alHi);
        const unsigned long long BE = pk2(beLo, beHi);
        #pragma unroll
        for (int j = 0; j < 32; j++) {
            float2 v = upk2(a[j]);
            a[j] = fma2(AL, pk2(v.x, v.x), mul2(BE, pk2(v.y, v.y)));
        }
    }

    // ---------- CZ sign masks ----------
    const unsigned long long BOTH = 0x8000000080000000ULL;
    const unsigned long long HI   = 0x8000000000000000ULL;
    const int lw = (lane >> 1) & 0xF;
    const int plane = __popc(lw & (lw >> 1)) & 1;
    const unsigned long long mlane =
        (plane ? BOTH : 0ULL) ^ (((lane >> 1) & 1) ? HI : 0ULL);

    // CZ of layer 0
    #pragma unroll
    for (int j = 0; j < 32; j++) {
        unsigned long long mj = ((j & 16) ? HI : 0ULL)
                              ^ ((__popc(j & (j >> 1)) & 1) ? BOTH : 0ULL);
        a[j] ^= mlane ^ mj;
    }

    // ---------- layers 1..5: fast-Givens gates ----------
    for (int d = 1; d < CDEPTH; ++d) {
        const float* gt = g_t + d * NQ;

        // fused: lane wire q (shfl, 1 fma2/amp) + reg wire 5+q (2 fma2/pair)
        #pragma unroll
        for (int q = 0; q < 4; q++) {
            const float tl = gt[q];
            const int   bit  = (lane >> (4 - q)) & 1;
            const int   dist = 1 << (4 - q);
            const float tv = bit ? tl : -tl;
            const unsigned long long tv2 = pk2(tv, tv);
            const float trg = gt[q + 5];
            const unsigned long long trp = pk2(trg, trg);
            const unsigned long long trn = trp ^ BOTH;   // negated via sign XOR
            const int p = 4 - q;

            #pragma unroll
            for (int j = 0; j < 32; j++) {
                if (j & (1 << p)) continue;
                const int j1 = j | (1 << p);
                unsigned long long o0 = __shfl_xor_sync(0xFFFFFFFFu, a[j],  dist);
                unsigned long long o1 = __shfl_xor_sync(0xFFFFFFFFu, a[j1], dist);
                unsigned long long A0 = fma2(tv2, o0, a[j]);    // lane gate (scaled)
                unsigned long long A1 = fma2(tv2, o1, a[j1]);
                a[j]  = fma2(trn, A1, A0);                      // reg gate (scaled)
                a[j1] = fma2(trp, A0, A1);
            }
        }

        // tail: pack-bit wire 4 (half-swap) + reg wire 9 (bit 0)
        {
            const float t4 = gt[4];
            const unsigned long long sp = pk2(-t4, t4);   // lo: -t*hi ; hi: +t*lo
            const float t9 = gt[9];
            const unsigned long long t9p = pk2(t9, t9);
            const unsigned long long t9n = t9p ^ BOTH;
            #pragma unroll
            for (int j = 0; j < 32; j += 2) {
                unsigned long long B0 = fma2(sp, swap2(a[j]),     a[j]);
                unsigned long long B1 = fma2(sp, swap2(a[j + 1]), a[j + 1]);
                a[j]     = fma2(t9n, B1, B0);
                a[j + 1] = fma2(t9p, B0, B1);
            }
        }

        // CZ chain -- skip after the last layer
        if (d != CDEPTH - 1) {
            #pragma unroll
            for (int j = 0; j < 32; j++) {
                unsigned long long mj = ((j & 16) ? HI : 0ULL)
                                      ^ ((__popc(j & (j >> 1)) & 1) ? BOTH : 0ULL);
                a[j] ^= mlane ^ mj;
            }
        }
    }

    // ---------- probabilities and Z-expectations (raw scale; *C2 later) ----------
    float tot = 0.f, z4 = 0.f, z5 = 0.f, z6 = 0.f, z7 = 0.f, z8 = 0.f, z9 = 0.f;
    #pragma unroll
    for (int j = 0; j < 32; j++) {
        float2 v = upk2(mul2(a[j], a[j]));
        float s = v.x + v.y;
        float dd = v.x - v.y;
        tot += s;  z4 += dd;
        z5 += (j & 16) ? -s : s;
        z6 += (j & 8)  ? -s : s;
        z7 += (j & 4)  ? -s : s;
        z8 += (j & 2)  ? -s : s;
        z9 += (j & 1)  ? -s : s;
    }
    #pragma unroll
    for (int st = 1; st < 32; st <<= 1) {
        z4 += __shfl_xor_sync(0xFFFFFFFFu, z4, st);
        z5 += __shfl_xor_sync(0xFFFFFFFFu, z5, st);
        z6 += __shfl_xor_sync(0xFFFFFFFFu, z6, st);
        z7 += __shfl_xor_sync(0xFFFFFFFFu, z7, st);
        z8 += __shfl_xor_sync(0xFFFFFFFFu, z8, st);
        z9 += __shfl_xor_sync(0xFFFFFFFFu, z9, st);
    }
    float E[NQ];
    #pragma unroll
    for (int q = 0; q < 4; q++) {
        const int m = 4 - q;
        float g = tot;
        float o = __shfl_xor_sync(0xFFFFFFFFu, g, 1 << m);
        g = ((lane >> m) & 1) ? (o - g) : (g - o);
        #pragma unroll
        for (int st = 1; st < 32; st <<= 1) {
            if (st != (1 << m)) g += __shfl_xor_sync(0xFFFFFFFFu, g, st);
        }
        E[q] = g;
    }
    E[4] = z4; E[5] = z5; E[6] = z6; E[7] = z7; E[8] = z8; E[9] = z9;

    // restore the factored-out cos^2 product
    const float C2 = g_C2;
    #pragma unroll
    for (int q = 0; q < NQ; q++) E[q] *= C2;

    // ---------- linear head ----------
    if (lane < NCLS) {
        float acc = b_cls[lane];
        #pragma unroll
        for (int q = 0; q < NQ; q++)
            acc += E[q] * w_cls[lane * NQ + q];
        out[e * NCLS + lane] = acc;
    }
}

extern "C" void kernel_launch(void* const* d_in, const int* in_sizes, int n_in,
                              void* d_out, int out_size) {
    const float* x      = (const float*)d_in[0];
    const float* params = (const float*)d_in[1];
    const float* w_cls  = (const float*)d_in[2];
    const float* b_cls  = (const float*)d_in[3];
    float* out = (float*)d_out;

    precompute_gates<<<1, 64>>>(params);
    qsim_kernel<<<CBATCH / 8, 256>>>(x, w_cls, b_cls, out);
}